// round 17
// baseline (speedup 1.0000x reference)
#include <cuda_runtime.h>

// QPChargeNormalization — FINAL architecture (measured best lineage:
// R8 55.2us -> R12 55.1us kernel, 82.7% DRAM, 6.56 TB/s).
//
// Per row b (B=4096): n=8192, c=[c_iso|c_aniso], q=[int_iso|int_aniso]
//   h = (sum(charge[b]) - q.c) / (q.q),  x = c + h*q
// Output = [sol_iso (B*4096) | sol_aniso (B*4096)]
//
// One CTA per row, 512 threads, 2 CTAs/SM, all 32 data floats per thread
// register-resident between the reduction and the axpy — each element
// crosses HBM exactly once (406 MB @ ~7.3 TB/s effective).
//
// This round: balanced warp load — every thread reads 0.5*charge[t&255]
// (duplicate read is an L1/L2 line broadcast, zero extra DRAM traffic),
// so all 16 warps issue the same 9 loads and run the identical 3-value
// butterfly; no predicate, no warp-uniform branch. Single __syncthreads
// per row; every warp redundantly reduces the 16 partials to form h.

#define NTHREADS 512
#define NCH      256

__device__ __forceinline__ float dot4(float4 a, float4 b) {
    return fmaf(a.x, b.x, fmaf(a.y, b.y, fmaf(a.z, b.z, a.w * b.w)));
}

__device__ __forceinline__ float4 axpy4(float h, float4 q, float4 c) {
    float4 o;
    o.x = fmaf(h, q.x, c.x);
    o.y = fmaf(h, q.y, c.y);
    o.z = fmaf(h, q.z, c.z);
    o.w = fmaf(h, q.w, c.w);
    return o;
}

__global__ void __launch_bounds__(NTHREADS, 2)
qp_charge_norm_kernel(const float4* __restrict__ c_iso,
                      const float4* __restrict__ c_aniso,
                      const float4* __restrict__ q_iso,
                      const float4* __restrict__ q_aniso,
                      const float*  __restrict__ charge,
                      float4*       __restrict__ out,
                      int B)
{
    const int b    = blockIdx.x;
    const int t    = threadIdx.x;
    const int wid  = t >> 5;
    const int lane = t & 31;
    const size_t row4 = (size_t)b * 1024;   // float4 per 4096-float half-row

    const float4* ci = c_iso   + row4;
    const float4* ca = c_aniso + row4;
    const float4* qi = q_iso   + row4;
    const float4* qa = q_aniso + row4;

    // 8 x float4 loads per thread, front-batched for MLP.
    float4 c0 = ci[t];
    float4 c1 = ci[t + NTHREADS];
    float4 c2 = ca[t];
    float4 c3 = ca[t + NTHREADS];
    float4 q0 = qi[t];
    float4 q1 = qi[t + NTHREADS];
    float4 q2 = qa[t];
    float4 q3 = qa[t + NTHREADS];

    // Every thread reads charge (t & 255): warps w and w+8 hit the same
    // 128B line, so this costs no extra DRAM traffic but balances all
    // warps at 9 loads and removes the t<256 predicate. The 0.5 factor
    // compensates for each entry being counted twice across 512 threads.
    float Qv = 0.5f * charge[(size_t)b * NCH + (t & (NCH - 1))];

    float qc = dot4(q0, c0) + dot4(q1, c1) + dot4(q2, c2) + dot4(q3, c3);
    float qq = dot4(q0, q0) + dot4(q1, q1) + dot4(q2, q2) + dot4(q3, q3);

    // Identical 3-value butterfly in every warp.
    #pragma unroll
    for (int m = 16; m; m >>= 1) {
        qc += __shfl_xor_sync(0xffffffffu, qc, m);
        qq += __shfl_xor_sync(0xffffffffu, qq, m);
        Qv += __shfl_xor_sync(0xffffffffu, Qv, m);
    }

    __shared__ float s_p[48];   // [0..16) qc, [16..32) qq, [32..48) Q
    if (lane == 0) { s_p[wid] = qc; s_p[16 + wid] = qq; s_p[32 + wid] = Qv; }
    __syncthreads();            // the ONLY barrier

    // Every warp redundantly reduces the 16 partials — no broadcast,
    // no second barrier.
    float sa = (lane < 16) ? s_p[lane]      : 0.0f;
    float sg = (lane < 16) ? s_p[16 + lane] : 0.0f;
    float sq = (lane < 16) ? s_p[32 + lane] : 0.0f;
    #pragma unroll
    for (int m = 8; m; m >>= 1) {
        sa += __shfl_xor_sync(0xffffffffu, sa, m);
        sg += __shfl_xor_sync(0xffffffffu, sg, m);
        sq += __shfl_xor_sync(0xffffffffu, sq, m);
    }
    const float h = __shfl_sync(0xffffffffu, (sq - sa) / sg, 0);

    float4* oi = out + row4;                      // iso block
    float4* oa = out + (size_t)B * 1024 + row4;   // aniso block

    oi[t]            = axpy4(h, q0, c0);
    oi[t + NTHREADS] = axpy4(h, q1, c1);
    oa[t]            = axpy4(h, q2, c2);
    oa[t + NTHREADS] = axpy4(h, q3, c3);
}

extern "C" void kernel_launch(void* const* d_in, const int* in_sizes, int n_in,
                              void* d_out, int out_size)
{
    const float4* c_iso   = (const float4*)d_in[0];
    const float4* c_aniso = (const float4*)d_in[1];
    const float4* q_iso   = (const float4*)d_in[2];
    const float4* q_aniso = (const float4*)d_in[3];
    const float*  charge  = (const float*) d_in[4];
    float4*       out     = (float4*)d_out;

    const int B = in_sizes[4] / NCH;   // charge is [B, 256]

    qp_charge_norm_kernel<<<B, NTHREADS>>>(c_iso, c_aniso, q_iso, q_aniso,
                                           charge, out, B);
}